// round 1
// baseline (speedup 1.0000x reference)
#include <cuda_runtime.h>

#define B_   256
#define R_   1152
#define C_   10
#define IC_  8
#define OC_  16
#define RT_  16
#define CHUNKS_ (R_/RT_)   /* 72 */

// Scratch (static device memory — no allocations).
__device__ __align__(16) float g_Vsum[B_*C_*OC_];                 // running sum of v_j
__device__ __align__(16) float g_scratch[CHUNKS_*B_*C_*OC_];      // per-r-chunk partial s

__global__ void init_kernel() {
    int i = blockIdx.x * blockDim.x + threadIdx.x;
    if (i < B_*C_*OC_) g_Vsum[i] = 0.0f;
}

// One fused routing pass. Grid: (CHUNKS_, 2), block 256.
// Thread -> (b = by*128 + tid/2, o-half = tid&1). Each thread owns s[10][8] in regs.
template<bool FIRST>
__global__ __launch_bounds__(256, 1)
void pass_kernel(const float* __restrict__ x, const float* __restrict__ w) {
    extern __shared__ float4 Ws[];            // [RT_][C_][IC_][4] float4 = 80 KB
    const int tid   = threadIdx.x;
    const int chunk = blockIdx.x;
    const int r0    = chunk * RT_;
    const int oh    = tid & 1;                // which 8-wide half of OC
    const int b     = blockIdx.y * 128 + (tid >> 1);

    // Cooperative load of the W tile for RT_ routes (coalesced, float4).
    const float4* wsrc = reinterpret_cast<const float4*>(w) + (size_t)r0 * (C_*IC_*4);
    for (int idx = tid; idx < RT_*C_*IC_*4; idx += 256) Ws[idx] = wsrc[idx];
    __syncthreads();

    float s[C_][8];
    #pragma unroll
    for (int c = 0; c < C_; ++c)
        #pragma unroll
        for (int j = 0; j < 8; ++j) s[c][j] = 0.0f;

    const float* xrow = x + ((size_t)b * R_ + r0) * IC_;
    const float* vsum = g_Vsum + b * (C_*OC_) + oh * 8;

    #pragma unroll 1
    for (int r = 0; r < RT_; ++r) {
        float4 xa = *reinterpret_cast<const float4*>(xrow + r*IC_);
        float4 xb = *reinterpret_cast<const float4*>(xrow + r*IC_ + 4);
        float xi[8] = {xa.x, xa.y, xa.z, xa.w, xb.x, xb.y, xb.z, xb.w};

        float u[C_][8];
        float t[C_];
        const float4* wr = &Ws[(size_t)r * (C_*IC_*4)];

        #pragma unroll
        for (int c = 0; c < C_; ++c) {
            float acc[8] = {0,0,0,0,0,0,0,0};
            #pragma unroll
            for (int i = 0; i < IC_; ++i) {
                float4 wA = wr[(c*IC_ + i)*4 + oh*2];       // smem broadcast loads
                float4 wB = wr[(c*IC_ + i)*4 + oh*2 + 1];
                acc[0] += xi[i]*wA.x; acc[1] += xi[i]*wA.y;
                acc[2] += xi[i]*wA.z; acc[3] += xi[i]*wA.w;
                acc[4] += xi[i]*wB.x; acc[5] += xi[i]*wB.y;
                acc[6] += xi[i]*wB.z; acc[7] += xi[i]*wB.w;
            }
            #pragma unroll
            for (int j = 0; j < 8; ++j) u[c][j] = acc[j];
            if (!FIRST) {
                float4 vA = *reinterpret_cast<const float4*>(vsum + c*OC_);
                float4 vB = *reinterpret_cast<const float4*>(vsum + c*OC_ + 4);
                t[c] = acc[0]*vA.x + acc[1]*vA.y + acc[2]*vA.z + acc[3]*vA.w
                     + acc[4]*vB.x + acc[5]*vB.y + acc[6]*vB.z + acc[7]*vB.w;
            }
        }

        float coef[C_];
        if (FIRST) {
            #pragma unroll
            for (int c = 0; c < C_; ++c) coef[c] = 0.1f;
        } else {
            // partner lane (same b, other o-half) completes the dot product
            #pragma unroll
            for (int c = 0; c < C_; ++c) t[c] += __shfl_xor_sync(0xffffffffu, t[c], 1);
            float m = t[0];
            #pragma unroll
            for (int c = 1; c < C_; ++c) m = fmaxf(m, t[c]);
            float sum = 0.0f;
            #pragma unroll
            for (int c = 0; c < C_; ++c) { coef[c] = __expf(t[c] - m); sum += coef[c]; }
            float inv = __fdividef(1.0f, sum);
            #pragma unroll
            for (int c = 0; c < C_; ++c) coef[c] *= inv;
        }

        #pragma unroll
        for (int c = 0; c < C_; ++c)
            #pragma unroll
            for (int j = 0; j < 8; ++j) s[c][j] += coef[c] * u[c][j];
    }

    // Write per-chunk partial s (no atomics; reduced in squash kernel).
    float* dst = g_scratch + ((size_t)chunk * B_ + b) * (C_*OC_) + oh * 8;
    #pragma unroll
    for (int c = 0; c < C_; ++c) {
        float4 pa = make_float4(s[c][0], s[c][1], s[c][2], s[c][3]);
        float4 pb = make_float4(s[c][4], s[c][5], s[c][6], s[c][7]);
        *reinterpret_cast<float4*>(dst + c*OC_)     = pa;
        *reinterpret_cast<float4*>(dst + c*OC_ + 4) = pb;
    }
}

// Reduce 72 partials, squash, update Vsum (or emit final output).
// Grid: 160 x 256 = 40960 threads, one per (b,c,o). 16-lane groups share (b,c).
template<bool LAST>
__global__ void squash_kernel(float* __restrict__ out) {
    int g = blockIdx.x * 256 + threadIdx.x;
    float s = 0.0f;
    #pragma unroll 8
    for (int k = 0; k < CHUNKS_; ++k) s += g_scratch[(size_t)k * (B_*C_*OC_) + g];
    float sq = s * s;
    #pragma unroll
    for (int m = 8; m >= 1; m >>= 1) sq += __shfl_xor_sync(0xffffffffu, sq, m);
    float n = sqrtf(sq);
    float v = (sq / (1.0f + sq)) * s / (n + 1e-8f);
    if (LAST) out[g] = v;
    else      g_Vsum[g] += v;
}

extern "C" void kernel_launch(void* const* d_in, const int* in_sizes, int n_in,
                              void* d_out, int out_size) {
    const float* x = (const float*)d_in[0];
    const float* w = (const float*)d_in[1];
    float* out = (float*)d_out;

    const size_t smem = (size_t)RT_ * C_ * IC_ * 4 * sizeof(float4);  // 81920 B
    cudaFuncSetAttribute(pass_kernel<true>,  cudaFuncAttributeMaxDynamicSharedMemorySize, (int)smem);
    cudaFuncSetAttribute(pass_kernel<false>, cudaFuncAttributeMaxDynamicSharedMemorySize, (int)smem);

    dim3 grid(CHUNKS_, 2);

    init_kernel<<<160, 256>>>();
    pass_kernel<true ><<<grid, 256, smem>>>(x, w);   // iter 1 (uniform coupling)
    squash_kernel<false><<<160, 256>>>(out);         // v1, Vsum = v1
    pass_kernel<false><<<grid, 256, smem>>>(x, w);   // iter 2
    squash_kernel<false><<<160, 256>>>(out);         // v2, Vsum = v1+v2
    pass_kernel<false><<<grid, 256, smem>>>(x, w);   // iter 3
    squash_kernel<true ><<<160, 256>>>(out);         // v3 -> output
}